// round 3
// baseline (speedup 1.0000x reference)
#include <cuda_runtime.h>
#include <cuda_bf16.h>

// SSIM over (32,3,512,512) fp32 pairs, 7x7 box filters, interior-crop mean.
// Fused single pass: horizontal incremental 7-sums (4 cols/thread) +
// vertical running sums over a 9-row raw ring in shared memory (1 bar/row).
// Final reduction fused via atomic ticket (deterministic fixed-order sum).

namespace {
constexpr int W = 512;
constexpr int H = 512;
constexpr int NCH = 96;              // 32 * 3
constexpr int STRIPS = 8;
constexpr int SROWS = H / STRIPS;    // 64 output rows per block
constexpr int TPB = 128;
constexpr int CPT = 4;               // output columns per thread (128*4 = 512)
constexpr int RINGW = 520;           // 518 used (x = -3..514), padded for float4 tail
constexpr int NSLOT = 9;             // ring slots; 9 => pre-store barrier provably redundant
constexpr int NBLOCKS = NCH * STRIPS;   // 768
constexpr int CROP_LO = 3;
constexpr int CROP_HI = 508;         // inclusive; 506 rows/cols survive the crop
constexpr float C1 = 1e-4f;          // (0.01*1)^2
constexpr float C2 = 9e-4f;          // (0.03*1)^2
}

__device__ float g_partials[NBLOCKS];
__device__ unsigned int g_ticket = 0;

// Load one image row (with x halo, zeros out of bounds) into registers.
__device__ __forceinline__ void prefetch_row(const float* __restrict__ p1,
                                             const float* __restrict__ p2,
                                             int r, int tid,
                                             float v1[5], float v2[5]) {
    const bool inr = ((unsigned)r < (unsigned)H);
    const float* row1 = p1 + (size_t)(inr ? r : 0) * W;
    const float* row2 = p2 + (size_t)(inr ? r : 0) * W;
#pragma unroll
    for (int k = 0; k < 5; k++) {
        int p = tid + k * TPB;       // ring position 0..517  (x = p - 3)
        int x = p - 3;
        float a = 0.f, b = 0.f;
        if (inr && p < W + 6 && (unsigned)x < (unsigned)W) {
            a = __ldg(row1 + x);
            b = __ldg(row2 + x);
        }
        v1[k] = a; v2[k] = b;
    }
}

__device__ __forceinline__ void store_row(float* __restrict__ d1,
                                          float* __restrict__ d2,
                                          int tid,
                                          const float v1[5], const float v2[5]) {
#pragma unroll
    for (int k = 0; k < 5; k++) {
        int p = tid + k * TPB;
        if (p < W + 6) { d1[p] = v1[k]; d2[p] = v2[k]; }
    }
}

// Accumulate (+/-) the 5 horizontal 7-sums for CPT consecutive outputs into vs.
// Reads 12 floats per image as 3 conflict-free LDS.128 (x0 is 16B aligned).
template <int SGN>
__device__ __forceinline__ void hsum_acc(const float* __restrict__ a,
                                         const float* __restrict__ b,
                                         int x0, float vs[5][CPT]) {
    float A[12], Bv[12];
    const float4* a4 = reinterpret_cast<const float4*>(a + x0);
    const float4* b4 = reinterpret_cast<const float4*>(b + x0);
#pragma unroll
    for (int q = 0; q < 3; q++) {
        float4 t = a4[q];
        A[4*q+0] = t.x; A[4*q+1] = t.y; A[4*q+2] = t.z; A[4*q+3] = t.w;
        float4 u = b4[q];
        Bv[4*q+0] = u.x; Bv[4*q+1] = u.y; Bv[4*q+2] = u.z; Bv[4*q+3] = u.w;
    }
    float s1 = 0.f, s2 = 0.f, s11 = 0.f, s22 = 0.f, s12 = 0.f;
#pragma unroll
    for (int i = 0; i < 7; i++) {
        s1 += A[i]; s2 += Bv[i];
        s11 = fmaf(A[i], A[i], s11);
        s22 = fmaf(Bv[i], Bv[i], s22);
        s12 = fmaf(A[i], Bv[i], s12);
    }
#pragma unroll
    for (int c = 0; c < CPT; c++) {
        if (c > 0) {                 // slide window one column to the right
            float an = A[c + 6], ao = A[c - 1];
            float bn = Bv[c + 6], bo = Bv[c - 1];
            s1 += an - ao;
            s2 += bn - bo;
            s11 += fmaf(an, an, -(ao * ao));
            s22 += fmaf(bn, bn, -(bo * bo));
            s12 += fmaf(an, bn, -(ao * bo));
        }
        if (SGN > 0) {
            vs[0][c] += s1; vs[1][c] += s2; vs[2][c] += s11;
            vs[3][c] += s22; vs[4][c] += s12;
        } else {
            vs[0][c] -= s1; vs[1][c] -= s2; vs[2][c] -= s11;
            vs[3][c] -= s22; vs[4][c] -= s12;
        }
    }
}

__global__ void __launch_bounds__(TPB) ssim_map_kernel(const float* __restrict__ img1,
                                                       const float* __restrict__ img2,
                                                       float* __restrict__ out) {
    __shared__ __align__(16) float r1[NSLOT][RINGW];
    __shared__ __align__(16) float r2[NSLOT][RINGW];
    __shared__ float wsum[TPB / 32];
    __shared__ int is_last_s;
    __shared__ double dsh[TPB];

    const int blk = blockIdx.x;
    const int ch = blk / STRIPS;
    const int strip = blk - ch * STRIPS;
    const int y0 = strip * SROWS;
    const float* p1 = img1 + (size_t)ch * (W * H);
    const float* p2 = img2 + (size_t)ch * (W * H);
    const int tid = threadIdx.x;
    const int x0 = tid * CPT;

    // Fill slots 0..6 with rows y0-3 .. y0+3 (zeros outside the image).
#pragma unroll 1
    for (int s = 0; s < 7; s++) {
        float v1[5], v2[5];
        prefetch_row(p1, p2, y0 - 3 + s, tid, v1, v2);
        store_row(r1[s], r2[s], tid, v1, v2);
    }
    __syncthreads();

    float vs[5][CPT];
#pragma unroll
    for (int q = 0; q < 5; q++)
#pragma unroll
        for (int c = 0; c < CPT; c++) vs[q][c] = 0.f;

#pragma unroll 1
    for (int s = 0; s < 7; s++)
        hsum_acc<1>(r1[s], r2[s], x0, vs);

    // Prefetch the first mainloop row one iteration ahead (hides DRAM latency).
    float pf1[5], pf2[5];
    prefetch_row(p1, p2, y0 + 4, tid, pf1, pf2);

    constexpr float P = 1.0f / 49.0f;
    constexpr float CN = 49.0f / 48.0f;
    float lsum = 0.f;
    int sn = 7;   // slot receiving entering row (y+3)
    int so = 0;   // slot holding leaving row  (y-4)

#pragma unroll 1
    for (int y = y0; y < y0 + SROWS; y++) {
        if (y > y0) {
            // Slot sn last held row y-6, last read at iteration y-2 (before the
            // y-1 barrier) -> safe to overwrite with only ONE barrier per row.
            store_row(r1[sn], r2[sn], tid, pf1, pf2);
            prefetch_row(p1, p2, y + 4, tid, pf1, pf2);  // next row in flight
            __syncthreads();
            hsum_acc<1>(r1[sn], r2[sn], x0, vs);         // + entering row y+3
            hsum_acc<-1>(r1[so], r2[so], x0, vs);        // - leaving row y-4
            sn = (sn + 1 == NSLOT) ? 0 : sn + 1;
            so = (so + 1 == NSLOT) ? 0 : so + 1;
        }
        if (y >= CROP_LO && y <= CROP_HI) {
#pragma unroll
            for (int c = 0; c < CPT; c++) {
                int x = x0 + c;
                if (x >= CROP_LO && x <= CROP_HI) {
                    float ux  = vs[0][c] * P, uy  = vs[1][c] * P;
                    float uxx = vs[2][c] * P, uyy = vs[3][c] * P, uxy = vs[4][c] * P;
                    float vx  = CN * (uxx - ux * ux);
                    float vy  = CN * (uyy - uy * uy);
                    float vxy = CN * (uxy - ux * uy);
                    float A1 = 2.f * ux * uy + C1;
                    float A2 = 2.f * vxy + C2;
                    float B1 = ux * ux + uy * uy + C1;
                    float B2 = vx + vy + C2;
                    lsum += __fdividef(A1 * A2, B1 * B2);
                }
            }
        }
    }

    // Deterministic block reduction: shfl within warp, fixed-order combine.
#pragma unroll
    for (int o = 16; o > 0; o >>= 1)
        lsum += __shfl_down_sync(0xffffffffu, lsum, o);
    if ((tid & 31) == 0) wsum[tid >> 5] = lsum;
    __syncthreads();
    if (tid == 0) {
        g_partials[blk] = (wsum[0] + wsum[1]) + (wsum[2] + wsum[3]);
        __threadfence();
        unsigned int t = atomicAdd(&g_ticket, 1u);
        is_last_s = (t == (unsigned)(NBLOCKS - 1)) ? 1 : 0;
    }
    __syncthreads();

    // Last block performs the deterministic final reduction (fixed index order).
    if (is_last_s) {
        __threadfence();
        double acc = 0.0;
#pragma unroll 1
        for (int i = tid; i < NBLOCKS; i += TPB) acc += (double)__ldcg(&g_partials[i]);
        dsh[tid] = acc;
        __syncthreads();
#pragma unroll 1
        for (int o = TPB / 2; o > 0; o >>= 1) {
            if (tid < o) dsh[tid] += dsh[tid + o];
            __syncthreads();
        }
        if (tid == 0) {
            const double crop = (double)(CROP_HI - CROP_LO + 1);
            out[0] = (float)(dsh[0] / ((double)NCH * crop * crop));
            g_ticket = 0;            // reset for next graph replay
        }
    }
}

extern "C" void kernel_launch(void* const* d_in, const int* in_sizes, int n_in,
                              void* d_out, int out_size) {
    (void)in_sizes; (void)n_in; (void)out_size;
    const float* img1 = (const float*)d_in[0];
    const float* img2 = (const float*)d_in[1];
    float* out = (float*)d_out;
    ssim_map_kernel<<<NBLOCKS, TPB>>>(img1, img2, out);
}

// round 5
// speedup vs baseline: 1.1354x; 1.1354x over previous
#include <cuda_runtime.h>
#include <cuda_bf16.h>

// SSIM over (32,3,512,512) fp32 pairs, 7x7 box, interior-crop mean.
// Issue-bound kernel -> packed f32x2 math on an interleaved float2 ring.

typedef unsigned long long u64;

namespace {
constexpr int W = 512;
constexpr int H = 512;
constexpr int NCH = 96;               // 32 * 3
constexpr int STRIPS = 8;
constexpr int SROWS = H / STRIPS;     // 64 rows per block
constexpr int TPB = 128;
constexpr int CPT = 4;                // output columns per thread
constexpr int RINGW = 520;            // float2 pairs per ring row (518 used)
constexpr int NSLOT = 9;              // 9 slots => single barrier per row is safe
constexpr int NBLOCKS = NCH * STRIPS; // 768
constexpr int CROP_LO = 3;
constexpr int CROP_HI = 508;          // inclusive
constexpr float C1 = 1e-4f;
constexpr float C2 = 9e-4f;
constexpr float P49 = 1.0f / 49.0f;
constexpr float CN = 49.0f / 48.0f;
}

__device__ float g_partials[NBLOCKS];
__device__ unsigned int g_ticket = 0;

// ---- packed fp32x2 helpers (sm_100a) ----
__device__ __forceinline__ u64 add2(u64 a, u64 b) {
    u64 r; asm("add.rn.f32x2 %0,%1,%2;" : "=l"(r) : "l"(a), "l"(b)); return r;
}
__device__ __forceinline__ u64 mul2(u64 a, u64 b) {
    u64 r; asm("mul.rn.f32x2 %0,%1,%2;" : "=l"(r) : "l"(a), "l"(b)); return r;
}
__device__ __forceinline__ u64 fma2(u64 a, u64 b, u64 c) {
    u64 r; asm("fma.rn.f32x2 %0,%1,%2,%3;" : "=l"(r) : "l"(a), "l"(b), "l"(c)); return r;
}
__device__ __forceinline__ u64 pk(float lo, float hi) {
    u64 r; asm("mov.b64 %0,{%1,%2};" : "=l"(r) : "f"(lo), "f"(hi)); return r;
}
__device__ __forceinline__ void upk(u64 v, float& lo, float& hi) {
    asm("mov.b64 {%0,%1},%2;" : "=f"(lo), "=f"(hi) : "l"(v));
}

// Load one interleaved image row (x halo, zeros OOB) into registers.
__device__ __forceinline__ void prefetch_row(const float* __restrict__ p1,
                                             const float* __restrict__ p2,
                                             int r, int tid, float2 v[5]) {
    const bool inr = ((unsigned)r < (unsigned)H);
    const float* row1 = p1 + (size_t)(inr ? r : 0) * W;
    const float* row2 = p2 + (size_t)(inr ? r : 0) * W;
#pragma unroll
    for (int k = 0; k < 5; k++) {
        int p = tid + k * TPB;        // ring position 0..517 (x = p - 3)
        int x = p - 3;
        float a = 0.f, b = 0.f;
        if (inr && p < W + 6 && (unsigned)x < (unsigned)W) {
            a = __ldg(row1 + x);
            b = __ldg(row2 + x);
        }
        v[k] = make_float2(a, b);
    }
}

__device__ __forceinline__ void store_row(float2* __restrict__ d, int tid,
                                          const float2 v[5]) {
#pragma unroll
    for (int k = 0; k < 5; k++) {
        int p = tid + k * TPB;
        if (p < W + 6) d[p] = v[k];   // STS.64
    }
}

// Accumulate (+/-) the packed horizontal 7-sums for CPT outputs.
// P = (sum x, sum y), Q = (sum x^2, sum y^2), s12 = sum x*y.
template <int SGN>
__device__ __forceinline__ void hsum_acc(const float2* __restrict__ row, int x0,
                                         u64 vsP[CPT], u64 vsQ[CPT],
                                         float vs12[CPT], u64 NEG1) {
    u64 pr[10];
    const ulonglong2* r2 = reinterpret_cast<const ulonglong2*>(row + x0);
#pragma unroll
    for (int q = 0; q < 5; q++) {     // 5x LDS.128, conflict-free
        ulonglong2 t = r2[q];
        pr[2 * q] = t.x; pr[2 * q + 1] = t.y;
    }
    u64 P = pr[0];
    u64 Q = mul2(pr[0], pr[0]);
    float a0, b0; upk(pr[0], a0, b0);
    float s12 = a0 * b0;
#pragma unroll
    for (int i = 1; i < 7; i++) {
        P = add2(P, pr[i]);
        Q = fma2(pr[i], pr[i], Q);
        float a, b; upk(pr[i], a, b);
        s12 = fmaf(a, b, s12);
    }
#pragma unroll
    for (int c = 0; c < CPT; c++) {
        if (c > 0) {                  // slide window right by one column
            u64 an = pr[c + 6], ao = pr[c - 1];
            P = fma2(ao, NEG1, add2(P, an));
            Q = fma2(mul2(ao, ao), NEG1, fma2(an, an, Q));
            float anx, any_, aox, aoy;
            upk(an, anx, any_); upk(ao, aox, aoy);
            s12 = fmaf(anx, any_, s12);
            s12 = fmaf(-aox, aoy, s12);
        }
        if (SGN > 0) {
            vsP[c] = add2(vsP[c], P);
            vsQ[c] = add2(vsQ[c], Q);
            vs12[c] += s12;
        } else {
            vsP[c] = fma2(P, NEG1, vsP[c]);
            vsQ[c] = fma2(Q, NEG1, vsQ[c]);
            vs12[c] -= s12;
        }
    }
}

__global__ void __launch_bounds__(TPB, 6)
ssim_map_kernel(const float* __restrict__ img1,
                const float* __restrict__ img2,
                float* __restrict__ out) {
    __shared__ __align__(16) float2 ring[NSLOT][RINGW];   // 37440 B
    __shared__ float wsum[TPB / 32];
    __shared__ int is_last_s;

    const int blk = blockIdx.x;
    const int ch = blk / STRIPS;
    const int strip = blk - ch * STRIPS;
    const int y0 = strip * SROWS;
    const float* p1 = img1 + (size_t)ch * (W * H);
    const float* p2 = img2 + (size_t)ch * (W * H);
    const int tid = threadIdx.x;
    const int x0 = tid * CPT;
    const u64 NEG1 = pk(-1.f, -1.f);

    // Fill slots 0..6 with rows y0-3 .. y0+3.
#pragma unroll 1
    for (int s = 0; s < 7; s++) {
        float2 v[5];
        prefetch_row(p1, p2, y0 - 3 + s, tid, v);
        store_row(ring[s], tid, v);
    }
    __syncthreads();

    u64 vsP[CPT], vsQ[CPT];
    float vs12[CPT];
    const u64 Z = pk(0.f, 0.f);
#pragma unroll
    for (int c = 0; c < CPT; c++) { vsP[c] = Z; vsQ[c] = Z; vs12[c] = 0.f; }

#pragma unroll 1
    for (int s = 0; s < 7; s++)
        hsum_acc<1>(ring[s], x0, vsP, vsQ, vs12, NEG1);

    // Prefetch the first mainloop row one iteration ahead.
    float2 pf[5];
    prefetch_row(p1, p2, y0 + 4, tid, pf);

    const u64 PP = pk(P49, P49);
    float lsum = 0.f;
    int sn = 7;   // slot receiving entering row (y+3)
    int so = 0;   // slot holding leaving row  (y-4)

#pragma unroll 1
    for (int y = y0; y < y0 + SROWS; y++) {
        if (y > y0) {
            // Slot sn last held row y-6, last read at iteration y-2 (before
            // iteration y-1's barrier) -> one barrier per row suffices.
            store_row(ring[sn], tid, pf);
            prefetch_row(p1, p2, y + 4, tid, pf);
            __syncthreads();
            hsum_acc<1>(ring[sn], x0, vsP, vsQ, vs12, NEG1);   // + row y+3
            hsum_acc<-1>(ring[so], x0, vsP, vsQ, vs12, NEG1);  // - row y-4
            sn = (sn + 1 == NSLOT) ? 0 : sn + 1;
            so = (so + 1 == NSLOT) ? 0 : so + 1;
        }
        if (y >= CROP_LO && y <= CROP_HI) {
#pragma unroll
            for (int c = 0; c < CPT; c++) {
                int x = x0 + c;
                if (x >= CROP_LO && x <= CROP_HI) {
                    u64 u = mul2(vsP[c], PP);    // (ux, uy)
                    u64 uq = mul2(vsQ[c], PP);   // (uxx, uyy)
                    float uxy = vs12[c] * P49;
                    float ux, uy, uxx, uyy;
                    upk(u, ux, uy); upk(uq, uxx, uyy);
                    float SP = ux * uy;
                    float SS = fmaf(ux, ux, uy * uy);
                    float T  = uxx + uyy;
                    float A1 = fmaf(2.f, SP, C1);
                    float B1 = SS + C1;
                    float A2 = fmaf(2.f * CN, uxy - SP, C2);
                    float B2 = fmaf(CN, T - SS, C2);
                    lsum += __fdividef(A1 * A2, B1 * B2);
                }
            }
        }
    }

    // Deterministic block reduction.
#pragma unroll
    for (int o = 16; o > 0; o >>= 1)
        lsum += __shfl_down_sync(0xffffffffu, lsum, o);
    if ((tid & 31) == 0) wsum[tid >> 5] = lsum;
    __syncthreads();
    if (tid == 0) {
        g_partials[blk] = (wsum[0] + wsum[1]) + (wsum[2] + wsum[3]);
        __threadfence();
        unsigned int t = atomicAdd(&g_ticket, 1u);
        is_last_s = (t == (unsigned)(NBLOCKS - 1)) ? 1 : 0;
    }
    __syncthreads();

    // Last block: deterministic fixed-order final reduction (reuses ring smem).
    if (is_last_s) {
        double* dsh = reinterpret_cast<double*>(&ring[0][0]);
        __threadfence();
        double acc = 0.0;
#pragma unroll 1
        for (int i = tid; i < NBLOCKS; i += TPB) acc += (double)__ldcg(&g_partials[i]);
        dsh[tid] = acc;
        __syncthreads();
#pragma unroll 1
        for (int o = TPB / 2; o > 0; o >>= 1) {
            if (tid < o) dsh[tid] += dsh[tid + o];
            __syncthreads();
        }
        if (tid == 0) {
            const double crop = (double)(CROP_HI - CROP_LO + 1);
            out[0] = (float)(dsh[0] / ((double)NCH * crop * crop));
            g_ticket = 0;   // reset for next graph replay
        }
    }
}

extern "C" void kernel_launch(void* const* d_in, const int* in_sizes, int n_in,
                              void* d_out, int out_size) {
    (void)in_sizes; (void)n_in; (void)out_size;
    const float* img1 = (const float*)d_in[0];
    const float* img2 = (const float*)d_in[1];
    float* out = (float*)d_out;
    ssim_map_kernel<<<NBLOCKS, TPB>>>(img1, img2, out);
}

// round 6
// speedup vs baseline: 1.1552x; 1.0175x over previous
#include <cuda_runtime.h>
#include <cuda_bf16.h>
#include <cstdint>

// SSIM over (32,3,512,512) fp32 pairs, 7x7 box, interior-crop mean.
// Packed f32x2 math on an interleaved float2 ring; XOR-swizzled smem
// (conflict-free LDS.128 at 32B lane stride) + vectorized LDG.128 row loads.

typedef unsigned long long u64;

namespace {
constexpr int W = 512;
constexpr int H = 512;
constexpr int NCH = 96;               // 32 * 3
constexpr int STRIPS = 8;
constexpr int SROWS = H / STRIPS;     // 64 rows per block
constexpr int TPB = 128;
constexpr int CPT = 4;                // output columns per thread
constexpr int RINGW = 520;            // float2 slots per ring row (518 used)
constexpr int ROWB = RINGW * 8;       // 4160 bytes per ring row
constexpr int NSLOT = 9;              // 9 slots => single barrier per row safe
constexpr int NBLOCKS = NCH * STRIPS; // 768
constexpr int CROP_LO = 3;
constexpr int CROP_HI = 508;          // inclusive
constexpr float C1 = 1e-4f;
constexpr float C2 = 9e-4f;
constexpr float P49 = 1.0f / 49.0f;
constexpr float CN = 49.0f / 48.0f;
}

__device__ float g_partials[NBLOCKS];
__device__ unsigned int g_ticket = 0;

// ---- packed fp32x2 helpers (sm_100a) ----
__device__ __forceinline__ u64 add2(u64 a, u64 b) {
    u64 r; asm("add.rn.f32x2 %0,%1,%2;" : "=l"(r) : "l"(a), "l"(b)); return r;
}
__device__ __forceinline__ u64 mul2(u64 a, u64 b) {
    u64 r; asm("mul.rn.f32x2 %0,%1,%2;" : "=l"(r) : "l"(a), "l"(b)); return r;
}
__device__ __forceinline__ u64 fma2(u64 a, u64 b, u64 c) {
    u64 r; asm("fma.rn.f32x2 %0,%1,%2,%3;" : "=l"(r) : "l"(a), "l"(b), "l"(c)); return r;
}
__device__ __forceinline__ u64 pk(float lo, float hi) {
    u64 r; asm("mov.b64 %0,{%1,%2};" : "=l"(r) : "f"(lo), "f"(hi)); return r;
}
__device__ __forceinline__ void upk(u64 v, float& lo, float& hi) {
    asm("mov.b64 {%0,%1},%2;" : "=f"(lo), "=f"(hi) : "l"(v));
}

// Chunk-preserving XOR swizzle: fold addr bit7 into bit4. Makes 32B-lane-stride
// LDS.128 / STS.128 phases hit 8 distinct 4-bank groups -> conflict-free.
__device__ __forceinline__ uint32_t sw(uint32_t off) {
    return off ^ ((off >> 3) & 0x10u);
}

// Load one row: this thread's 4 owned columns from both images (zeros if OOB row).
__device__ __forceinline__ void prefetch_row(const float* __restrict__ p1,
                                             const float* __restrict__ p2,
                                             int r, int tid, float4& a, float4& b) {
    if ((unsigned)r < (unsigned)H) {
        a = __ldg(reinterpret_cast<const float4*>(p1 + (size_t)r * W) + tid);
        b = __ldg(reinterpret_cast<const float4*>(p2 + (size_t)r * W) + tid);
    } else {
        a = make_float4(0.f, 0.f, 0.f, 0.f);
        b = make_float4(0.f, 0.f, 0.f, 0.f);
    }
}

// Store this thread's 4 interleaved pairs at ring idx 4t+3..4t+6 (swizzled).
__device__ __forceinline__ void store_row(char* __restrict__ ring, uint32_t slotbase,
                                          int tid, const float4& a, const float4& b) {
    uint32_t off = slotbase + (uint32_t)tid * 32u + 24u;   // byte of idx 4t+3
    *reinterpret_cast<float2*>(ring + sw(off))      = make_float2(a.x, b.x);
    *reinterpret_cast<float4*>(ring + sw(off + 8))  = make_float4(a.y, b.y, a.z, b.z);
    *reinterpret_cast<float2*>(ring + sw(off + 24)) = make_float2(a.w, b.w);
}

// Accumulate (+/-) packed horizontal 7-sums for CPT outputs.
// P = (sum x, sum y), Q = (sum x^2, sum y^2), s12 = sum x*y.
template <int SGN>
__device__ __forceinline__ void hsum_acc(const char* __restrict__ ring, uint32_t slotbase,
                                         int tid, u64 vsP[CPT], u64 vsQ[CPT],
                                         float vs12[CPT], u64 NEG1) {
    u64 pr[10];
    uint32_t base = slotbase + (uint32_t)tid * 32u;        // idx 4t, 16B aligned
#pragma unroll
    for (int q = 0; q < 5; q++) {                          // 5x LDS.128, swizzled
        ulonglong2 t2 = *reinterpret_cast<const ulonglong2*>(ring + sw(base + 16u * q));
        pr[2 * q] = t2.x; pr[2 * q + 1] = t2.y;
    }
    u64 P = pr[0];
    u64 Q = mul2(pr[0], pr[0]);
    float a0, b0; upk(pr[0], a0, b0);
    float s12 = a0 * b0;
#pragma unroll
    for (int i = 1; i < 7; i++) {
        P = add2(P, pr[i]);
        Q = fma2(pr[i], pr[i], Q);
        float a, b; upk(pr[i], a, b);
        s12 = fmaf(a, b, s12);
    }
#pragma unroll
    for (int c = 0; c < CPT; c++) {
        if (c > 0) {                  // slide window right by one column
            u64 an = pr[c + 6], ao = pr[c - 1];
            P = fma2(ao, NEG1, add2(P, an));
            Q = fma2(mul2(ao, ao), NEG1, fma2(an, an, Q));
            float anx, any_, aox, aoy;
            upk(an, anx, any_); upk(ao, aox, aoy);
            s12 = fmaf(anx, any_, s12);
            s12 = fmaf(-aox, aoy, s12);
        }
        if (SGN > 0) {
            vsP[c] = add2(vsP[c], P);
            vsQ[c] = add2(vsQ[c], Q);
            vs12[c] += s12;
        } else {
            vsP[c] = fma2(P, NEG1, vsP[c]);
            vsQ[c] = fma2(Q, NEG1, vsQ[c]);
            vs12[c] -= s12;
        }
    }
}

__global__ void __launch_bounds__(TPB, 6)
ssim_map_kernel(const float* __restrict__ img1,
                const float* __restrict__ img2,
                float* __restrict__ out) {
    __shared__ __align__(256) char ring[NSLOT * ROWB];     // 37440 B
    __shared__ float wsum[TPB / 32];
    __shared__ int is_last_s;

    const int blk = blockIdx.x;
    const int ch = blk / STRIPS;
    const int strip = blk - ch * STRIPS;
    const int y0 = strip * SROWS;
    const float* p1 = img1 + (size_t)ch * (W * H);
    const float* p2 = img2 + (size_t)ch * (W * H);
    const int tid = threadIdx.x;
    const u64 NEG1 = pk(-1.f, -1.f);

    // Zero the 6 halo cells (idx 0..2, 515..517) of every slot once.
    // Mainloop stores touch only idx 3..514, so these stay zero forever.
    if (tid < NSLOT * 6) {
        int s = tid / 6, j = tid % 6;
        uint32_t idx = (j < 3) ? (uint32_t)j : (uint32_t)(512 + j);
        *reinterpret_cast<float2*>(ring + sw((uint32_t)s * ROWB + idx * 8u)) =
            make_float2(0.f, 0.f);
    }

    // Fill slots 0..6 with rows y0-3 .. y0+3.
#pragma unroll 1
    for (int s = 0; s < 7; s++) {
        float4 a, b;
        prefetch_row(p1, p2, y0 - 3 + s, tid, a, b);
        store_row(ring, (uint32_t)s * ROWB, tid, a, b);
    }
    __syncthreads();

    u64 vsP[CPT], vsQ[CPT];
    float vs12[CPT];
    const u64 Z = pk(0.f, 0.f);
#pragma unroll
    for (int c = 0; c < CPT; c++) { vsP[c] = Z; vsQ[c] = Z; vs12[c] = 0.f; }

#pragma unroll 1
    for (int s = 0; s < 7; s++)
        hsum_acc<1>(ring, (uint32_t)s * ROWB, tid, vsP, vsQ, vs12, NEG1);

    // Prefetch the first mainloop row one iteration ahead.
    float4 pfa, pfb;
    prefetch_row(p1, p2, y0 + 4, tid, pfa, pfb);

    const u64 PP = pk(P49, P49);
    float lsum = 0.f;
    int sn = 7;   // slot receiving entering row (y+3)
    int so = 0;   // slot holding leaving row  (y-4)

#pragma unroll 1
    for (int y = y0; y < y0 + SROWS; y++) {
        if (y > y0) {
            // Slot sn last held row y-6, last read at iteration y-2 (before
            // iteration y-1's barrier) -> one barrier per row suffices.
            store_row(ring, (uint32_t)sn * ROWB, tid, pfa, pfb);
            prefetch_row(p1, p2, y + 4, tid, pfa, pfb);
            __syncthreads();
            hsum_acc<1>(ring, (uint32_t)sn * ROWB, tid, vsP, vsQ, vs12, NEG1);
            hsum_acc<-1>(ring, (uint32_t)so * ROWB, tid, vsP, vsQ, vs12, NEG1);
            sn = (sn + 1 == NSLOT) ? 0 : sn + 1;
            so = (so + 1 == NSLOT) ? 0 : so + 1;
        }
        if (y >= CROP_LO && y <= CROP_HI) {
            const int x0 = tid * CPT;
#pragma unroll
            for (int c = 0; c < CPT; c++) {
                int x = x0 + c;
                if (x >= CROP_LO && x <= CROP_HI) {
                    u64 u = mul2(vsP[c], PP);    // (ux, uy)
                    u64 uq = mul2(vsQ[c], PP);   // (uxx, uyy)
                    float uxy = vs12[c] * P49;
                    float ux, uy, uxx, uyy;
                    upk(u, ux, uy); upk(uq, uxx, uyy);
                    float SP = ux * uy;
                    float SS = fmaf(ux, ux, uy * uy);
                    float T  = uxx + uyy;
                    float A1 = fmaf(2.f, SP, C1);
                    float B1 = SS + C1;
                    float A2 = fmaf(2.f * CN, uxy - SP, C2);
                    float B2 = fmaf(CN, T - SS, C2);
                    lsum += __fdividef(A1 * A2, B1 * B2);
                }
            }
        }
    }

    // Deterministic block reduction.
#pragma unroll
    for (int o = 16; o > 0; o >>= 1)
        lsum += __shfl_down_sync(0xffffffffu, lsum, o);
    if ((tid & 31) == 0) wsum[tid >> 5] = lsum;
    __syncthreads();
    if (tid == 0) {
        g_partials[blk] = (wsum[0] + wsum[1]) + (wsum[2] + wsum[3]);
        __threadfence();
        unsigned int t = atomicAdd(&g_ticket, 1u);
        is_last_s = (t == (unsigned)(NBLOCKS - 1)) ? 1 : 0;
    }
    __syncthreads();

    // Last block: deterministic fixed-order final reduction (reuses ring smem).
    if (is_last_s) {
        double* dsh = reinterpret_cast<double*>(ring);
        __threadfence();
        double acc = 0.0;
#pragma unroll 1
        for (int i = tid; i < NBLOCKS; i += TPB) acc += (double)__ldcg(&g_partials[i]);
        dsh[tid] = acc;
        __syncthreads();
#pragma unroll 1
        for (int o = TPB / 2; o > 0; o >>= 1) {
            if (tid < o) dsh[tid] += dsh[tid + o];
            __syncthreads();
        }
        if (tid == 0) {
            const double crop = (double)(CROP_HI - CROP_LO + 1);
            out[0] = (float)(dsh[0] / ((double)NCH * crop * crop));
            g_ticket = 0;   // reset for next graph replay
        }
    }
}

extern "C" void kernel_launch(void* const* d_in, const int* in_sizes, int n_in,
                              void* d_out, int out_size) {
    (void)in_sizes; (void)n_in; (void)out_size;
    const float* img1 = (const float*)d_in[0];
    const float* img2 = (const float*)d_in[1];
    float* out = (float*)d_out;
    ssim_map_kernel<<<NBLOCKS, TPB>>>(img1, img2, out);
}